// round 16
// baseline (speedup 1.0000x reference)
#include <cuda_runtime.h>
#include <cuda_fp16.h>
#include <math.h>
#include <cstdint>

#define HW      96
#define NPIX    9216
#define NCH     21
#define RAD     35
#define KW      71
#define KSPLIT  4
#define KSLICE  2304
#define CHUNK   128
#define NCHUNK  18
#define NSTAGE  3
#define A_STRIDE 144
#define A_PANEL (256 * A_STRIDE)
#define B_PANEL 4096
#define STAGE_BYTES (A_PANEL + 2 * B_PANEL)  // 45056
#define RP      72
#define GTILES  36
#define NCTA    (GTILES * KSPLIT)            // 144
#define DYN_SMEM (NSTAGE * STAGE_BYTES + 1024)
#define STRIPS  6
#define SROWS   16
#define HALO    86
#define TROW    (HW + 2 * RAD)
#define NCONV   (NCH * STRIPS)
#define NITER   5
#define BSCALE  (4.0f / 255.0f)

// ---------------- device scratch ----------------
__device__ unsigned char g_Ku[(size_t)NPIX * NPIX];
__device__ float  g_rowpart[NPIX * RP];
__device__ float  g_rowinv[NPIX];
__device__ float  g_U[NCH * NPIX];
__device__ float  g_q[NCH * NPIX];
__device__ __half g_qh0[32 * NPIX];
__device__ __half g_qh1[32 * NPIX];
__device__ float  g_part[KSPLIT * NCH * NPIX];
__device__ float  g_qsf[NCH * NPIX];
__device__ float  g_g1d[KW];
__device__ int    g_tick[GTILES];
__device__ int    g_cnt;
__device__ int    g_bar;
__device__ int    g_gen;

// ---------------- PTX helpers ----------------
__device__ __forceinline__ uint32_t s2u(const void* p) {
    uint32_t a;
    asm("{ .reg .u64 t; cvta.to.shared.u64 t, %1; cvt.u32.u64 %0, t; }" : "=r"(a) : "l"(p));
    return a;
}
#define SWZ(b) ((b) ^ (((b) >> 3) & 0x70))
#define CP16(dst, src) \
    asm volatile("cp.async.cg.shared.global [%0], [%1], 16;" :: "r"(dst), "l"(src) : "memory")
#define CP_COMMIT() asm volatile("cp.async.commit_group;" ::: "memory")
#define CP_WAIT(n)  asm volatile("cp.async.wait_group %0;" :: "n"(n) : "memory")
#define BARG() asm volatile("bar.sync 1, 256;" ::: "memory")
#define BARC() asm volatile("bar.sync 2, 256;" ::: "memory")
#define LDSU16(r, addr) \
    asm volatile("ld.shared.u16 %0, [%1];" : "=r"(r) : "r"(addr))
#define LDSM4(r0, r1, r2, r3, addr) \
    asm volatile("ldmatrix.sync.aligned.m8n8.x4.shared.b16 {%0,%1,%2,%3}, [%4];" \
                 : "=r"(r0), "=r"(r1), "=r"(r2), "=r"(r3) : "r"(addr))
#define LDSM2(r0, r1, addr) \
    asm volatile("ldmatrix.sync.aligned.m8n8.x2.shared.b16 {%0,%1}, [%2];" \
                 : "=r"(r0), "=r"(r1) : "r"(addr))
#define MMA16816(d, a0, a1, a2, a3, b0, b1) \
    asm volatile("mma.sync.aligned.m16n8k16.row.col.f32.f16.f16.f32 " \
                 "{%0,%1,%2,%3}, {%4,%5,%6,%7}, {%8,%9}, {%0,%1,%2,%3};" \
                 : "+f"((d)[0]), "+f"((d)[1]), "+f"((d)[2]), "+f"((d)[3]) \
                 : "r"(a0), "r"(a1), "r"(a2), "r"(a3), "r"(b0), "r"(b1))

__device__ __forceinline__ uint32_t u8x2_to_h2(uint32_t w) {
    uint32_t r;
    asm("prmt.b32 %0, %1, 0, 0x4140;" : "=r"(r) : "r"(w));
    r |= 0x64006400u;
    asm("sub.rn.f16x2 %0, %0, %1;" : "+r"(r) : "r"(0x64006400u));
    return r;
}

// ---------------- setup: symmetric K with inline features ----------------
__global__ void __launch_bounds__(256) k_K(const float* __restrict__ ref,
                                           const float* __restrict__ kstd) {
    const int a = blockIdx.y, b = blockIdx.x;
    if (a > b) return;
    __shared__ float fA[5][128], fB[5][128], nA[128], nB[128];
    __shared__ unsigned char sT[128 * 132];
    __shared__ float redR[16][128], redC[16][128];
    const int tid = threadIdx.x;
    const int tr = tid >> 4, tc = tid & 15;

    if (tid < 256) {
        int half = tid >> 7;              // 0 -> A rows, 1 -> B cols
        int l = tid & 127;
        int i = (half ? b : a) * 128 + l;
        int y = i / HW, x = i % HW;
        float f0 = (float)y / kstd[0];
        float f1 = (float)x / kstd[1];
        float f2 = ref[0 * NPIX + i] / kstd[2];
        float f3 = ref[1 * NPIX + i] / kstd[3];
        float f4 = ref[2 * NPIX + i] / kstd[4];
        float nh = -0.5f * (f0 * f0 + f1 * f1 + f2 * f2 + f3 * f3 + f4 * f4);
        if (half == 0) {
            fA[0][l] = f0; fA[1][l] = f1; fA[2][l] = f2; fA[3][l] = f3; fA[4][l] = f4;
            nA[l] = nh;
        } else {
            fB[0][l] = f0; fB[1][l] = f1; fB[2][l] = f2; fB[3][l] = f3; fB[4][l] = f4;
            nB[l] = nh;
        }
    }
    __syncthreads();

    float rf[5][8], nri[8];
#pragma unroll
    for (int i = 0; i < 8; ++i) {
#pragma unroll
        for (int d = 0; d < 5; ++d) rf[d][i] = fA[d][tr * 8 + i];
        nri[i] = nA[tr * 8 + i];
    }
    float rs[8];
#pragma unroll
    for (int i = 0; i < 8; ++i) rs[i] = 0.f;

#pragma unroll
    for (int jj = 0; jj < 8; ++jj) {
        const int c = tc * 8 + jj;
        const float c0 = fB[0][c], c1 = fB[1][c], c2 = fB[2][c],
                    c3 = fB[3][c], c4 = fB[4][c];
        const float ncj = nB[c];
        float cs = 0.f;
#pragma unroll
        for (int i = 0; i < 8; ++i) {
            float dot = nri[i] + ncj;
            dot = fmaf(rf[0][i], c0, dot);
            dot = fmaf(rf[1][i], c1, dot);
            dot = fmaf(rf[2][i], c2, dot);
            dot = fmaf(rf[3][i], c3, dot);
            dot = fmaf(rf[4][i], c4, dot);
            float v = __expf(dot);
            rs[i] += v;
            cs += v;
            sT[(tr * 8 + i) * 132 + c] = (unsigned char)__float2uint_rn(v * 255.0f);
        }
        redC[tr][c] = cs;
    }
#pragma unroll
    for (int i = 0; i < 8; ++i) redR[tc][tr * 8 + i] = rs[i];
    __syncthreads();

    if (tid < 128) {
        float sR = 0.f, sC = 0.f;
#pragma unroll
        for (int k = 0; k < 16; ++k) { sR += redR[k][tid]; sC += redC[k][tid]; }
        g_rowpart[(a * 128 + tid) * RP + b] = sR;
        if (a != b) g_rowpart[(b * 128 + tid) * RP + a] = sC;
    }

    for (int wid = tid; wid < 4096; wid += 256) {
        const int r = wid >> 5, wc = wid & 31;
        uint32_t v = *(const uint32_t*)(sT + r * 132 + wc * 4);
        *(uint32_t*)(g_Ku + (size_t)(a * 128 + r) * NPIX + b * 128 + wc * 4) = v;
    }
    if (a != b) {
        for (int wid = tid; wid < 4096; wid += 256) {
            const int c = wid >> 5, wr = wid & 31;
            uint32_t b0 = sT[(wr * 4 + 0) * 132 + c];
            uint32_t b1 = sT[(wr * 4 + 1) * 132 + c];
            uint32_t b2 = sT[(wr * 4 + 2) * 132 + c];
            uint32_t b3 = sT[(wr * 4 + 3) * 132 + c];
            uint32_t v = b0 | (b1 << 8) | (b2 << 16) | (b3 << 24);
            *(uint32_t*)(g_Ku + (size_t)(b * 128 + c) * NPIX + a * 128 + wr * 4) = v;
        }
    }
}

__global__ void k_init(const float* __restrict__ unary) {
    int i = blockIdx.x * blockDim.x + threadIdx.x;
    if (i >= NPIX) return;
    if (i == 0) { g_cnt = 0; g_bar = 0; g_gen = 0; }
    if (i < GTILES) g_tick[i] = 0;
    if (i < KW + 1 && i == 0) {
        float w[KW]; float s = 0.f;
        for (int t = 0; t < KW; ++t) {
            float d = (float)t - (float)RAD;
            w[t] = expf(-(d * d) / 72.0f); s += w[t];
        }
        float inv = 1.0f / s;
        for (int t = 0; t < KW; ++t) g_g1d[t] = w[t] * inv;
    }
    float s = 0.f;
    const float* p = g_rowpart + i * RP;
#pragma unroll
    for (int bq = 0; bq < RP; ++bq) s += p[bq];
    float ri = 1.0f / (sqrtf(s) + 1e-8f);
    g_rowinv[i] = ri;

    float L[NCH];
    float m = -1e30f;
#pragma unroll
    for (int c = 0; c < NCH; ++c) {
        float u = unary[c * NPIX + i];
        u = fminf(fmaxf(u, 1e-5f), 1.0f);
        float lu = logf(u);
        g_U[c * NPIX + i] = lu;
        L[c] = lu;
        m = fmaxf(m, lu);
    }
    float se = 0.f;
#pragma unroll
    for (int c = 0; c < NCH; ++c) { L[c] = __expf(L[c] - m); se += L[c]; }
    float inv = 1.0f / se;
#pragma unroll
    for (int c = 0; c < NCH; ++c) {
        float q = L[c] * inv;
        g_q[c * NPIX + i] = q;
        g_qh0[c * NPIX + i] = __float2half_rn(q * ri);
    }
#pragma unroll
    for (int c = NCH; c < 32; ++c) {
        g_qh0[c * NPIX + i] = __float2half_rn(0.f);
        g_qh1[c * NPIX + i] = __float2half_rn(0.f);
    }
}

// ---------------- persistent fused: 5 iterations, in-kernel grid barrier ----------------
__global__ void __launch_bounds__(512, 1) k_fused(float* __restrict__ out) {
    extern __shared__ char dynRaw[];
    __shared__ float sImg[HALO * HW];
    __shared__ float sTmp[SROWS * TROW];
    __shared__ float sWc[KW];
    __shared__ int sLast;

    const uint32_t dynb = (s2u(dynRaw) + 1023u) & ~1023u;
    const int tid = threadIdx.x;
    const int m0 = blockIdx.x * 256;
    const int bid = blockIdx.y * GTILES + blockIdx.x;

    for (int it = 0; it < NITER; ++it) {
        const int p = it & 1;
        const __half* qhR = p ? g_qh1 : g_qh0;
        __half* qhW = p ? g_qh0 : g_qh1;

        if (tid < 256) {
            // ================= GEMM warps =================
            const int w = tid >> 5, lid = tid & 31;
            const int zbase = blockIdx.y * KSLICE;
            const unsigned char* Abase = g_Ku + (size_t)m0 * NPIX + zbase;
            const __half* Bbase = qhR + zbase;

            auto load_chunk = [&](int ci) {
                const uint32_t stage = dynb + (uint32_t)(ci % NSTAGE) * STAGE_BYTES;
                const int koff = ci * CHUNK;
#pragma unroll
                for (int u = tid; u < 2560; u += 256) {
                    uint32_t dst; const void* src;
                    if (u < 2048) {
                        int r = u >> 3, t = u & 7;
                        src = Abase + (size_t)r * NPIX + koff + t * 16;
                        dst = stage + (uint32_t)(r * A_STRIDE + t * 16);
                    } else {
                        int v = u - 2048;
                        int pl = v >> 8, cc = (v >> 3) & 31, t = v & 7;
                        src = Bbase + (size_t)cc * NPIX + koff + pl * 64 + t * 8;
                        dst = stage + A_PANEL + (uint32_t)pl * B_PANEL
                            + SWZ((uint32_t)(cc * 128 + t * 16));
                    }
                    CP16(dst, src);
                }
                CP_COMMIT();
            };

            float acc[2][3][4];
#pragma unroll
            for (int f = 0; f < 2; ++f)
#pragma unroll
                for (int g = 0; g < 3; ++g)
#pragma unroll
                    for (int k = 0; k < 4; ++k) acc[f][g][k] = 0.f;

            for (int i = 0; i < NSTAGE - 1; ++i) load_chunk(i);

            const uint32_t aBase0 = (uint32_t)((w * 32 + (lid >> 2)) * A_STRIDE + (lid & 3) * 2);
            const uint32_t aBase1 = aBase0 + 16 * A_STRIDE;
            const uint32_t bRowOff01 = (uint32_t)(((lid & 7) + ((lid >> 4) << 3)) * 128) + (((lid >> 3) & 1) << 4);
            const uint32_t bRowOff2 = (uint32_t)((16 + (lid & 7)) * 128) + (((lid >> 3) & 1) << 4);

            for (int i = 0; i < NCHUNK; ++i) {
                if (i + NSTAGE - 1 < NCHUNK) CP_WAIT(NSTAGE - 2); else CP_WAIT(0);
                BARG();
                if (i + NSTAGE - 1 < NCHUNK) load_chunk(i + NSTAGE - 1);

                const uint32_t stage = dynb + (uint32_t)(i % NSTAGE) * STAGE_BYTES;
#pragma unroll
                for (int pl = 0; pl < 2; ++pl) {
                    const uint32_t aOff = stage + (uint32_t)pl * 64;
                    const uint32_t bufB = stage + A_PANEL + (uint32_t)pl * B_PANEL;
#pragma unroll
                    for (int ks = 0; ks < 4; ++ks) {
                        const uint32_t kb = (uint32_t)ks * 32;
                        uint32_t b00, b01, b10, b11, b20, b21;
                        LDSM4(b00, b01, b10, b11, bufB + SWZ(bRowOff01 + kb));
                        LDSM2(b20, b21, bufB + SWZ(bRowOff2 + kb));

                        const uint32_t ad0 = aOff + aBase0 + (uint32_t)ks * 16;
                        const uint32_t ad1 = aOff + aBase1 + (uint32_t)ks * 16;
                        uint32_t w0, w1, w2, w3, w4, w5, w6, w7;
                        LDSU16(w0, ad0);
                        LDSU16(w1, ad0 + 8 * A_STRIDE);
                        LDSU16(w2, ad0 + 8);
                        LDSU16(w3, ad0 + 8 * A_STRIDE + 8);
                        LDSU16(w4, ad1);
                        LDSU16(w5, ad1 + 8 * A_STRIDE);
                        LDSU16(w6, ad1 + 8);
                        LDSU16(w7, ad1 + 8 * A_STRIDE + 8);
                        const uint32_t a00 = u8x2_to_h2(w0);
                        const uint32_t a01 = u8x2_to_h2(w1);
                        const uint32_t a02 = u8x2_to_h2(w2);
                        const uint32_t a03 = u8x2_to_h2(w3);
                        const uint32_t a10 = u8x2_to_h2(w4);
                        const uint32_t a11 = u8x2_to_h2(w5);
                        const uint32_t a12 = u8x2_to_h2(w6);
                        const uint32_t a13 = u8x2_to_h2(w7);

                        MMA16816(acc[0][0], a00, a01, a02, a03, b00, b01);
                        MMA16816(acc[0][1], a00, a01, a02, a03, b10, b11);
                        MMA16816(acc[0][2], a00, a01, a02, a03, b20, b21);
                        MMA16816(acc[1][0], a10, a11, a12, a13, b00, b01);
                        MMA16816(acc[1][1], a10, a11, a12, a13, b10, b11);
                        MMA16816(acc[1][2], a10, a11, a12, a13, b20, b21);
                    }
                }
            }

            const int c0 = (lid & 3) * 2;
            float* pp = g_part + (size_t)blockIdx.y * (NCH * NPIX);
#pragma unroll
            for (int f = 0; f < 2; ++f) {
                const int row0 = m0 + w * 32 + f * 16 + (lid >> 2);
#pragma unroll
                for (int g = 0; g < 3; ++g) {
#pragma unroll
                    for (int k = 0; k < 4; ++k) {
                        int c = g * 8 + c0 + (k & 1);
                        int row = row0 + ((k >> 1) << 3);
                        if (c < NCH) pp[c * NPIX + row] = acc[f][g][k];
                    }
                }
            }
            __threadfence();
        } else if (bid < NCONV) {
            // ================= conv warps (256 threads) =================
            const int ctid = tid - 256;
            const int c = bid / STRIPS, strip = bid % STRIPS;
            const int y0 = strip * SROWS, rowLo = y0 - RAD;

            if (ctid < KW) sWc[ctid] = g_g1d[ctid];
            const float* src = g_q + c * NPIX;
            for (int px = ctid; px < HALO * HW; px += 256) {
                int r = px / HW, x = px - r * HW;
                int gr = rowLo + r;
                sImg[px] = (gr >= 0 && gr < HW) ? src[gr * HW + x] : 0.f;
            }
            for (int px = ctid; px < SROWS * TROW; px += 256) sTmp[px] = 0.f;
            BARC();

            float a[6];
#pragma unroll
            for (int j = 0; j < 6; ++j) a[j] = 0.f;
#pragma unroll
            for (int t = 0; t < KW; ++t) {
                const float wv = sWc[t];
                const int o = t * HW + ctid;
#pragma unroll
                for (int j = 0; j < 6; ++j)
                    a[j] = fmaf(wv, sImg[o + 256 * j], a[j]);
            }
#pragma unroll
            for (int j = 0; j < 6; ++j) {
                int px = ctid + 256 * j;
                int y = px / HW, x = px - y * HW;
                sTmp[y * TROW + RAD + x] = a[j];
            }
            BARC();

            int bix[6];
#pragma unroll
            for (int j = 0; j < 6; ++j) {
                int px = ctid + 256 * j;
                int y = px / HW, x = px - y * HW;
                bix[j] = y * TROW + x;
                a[j] = 0.f;
            }
#pragma unroll
            for (int t = 0; t < KW; ++t) {
                const float wv = sWc[t];
#pragma unroll
                for (int j = 0; j < 6; ++j)
                    a[j] = fmaf(wv, sTmp[bix[j] + t], a[j]);
            }
            float* dst = g_qsf + c * NPIX + y0 * HW;
#pragma unroll
            for (int j = 0; j < 6; ++j) dst[ctid + 256 * j] = a[j];
            __threadfence();
            BARC();
            if (ctid == 0) atomicAdd(&g_cnt, 1);
        }

        // ================= ticket + fused softmax update =================
        __syncthreads();
        if (tid == 0) {
            int old = atomicAdd(&g_tick[blockIdx.x], 1);
            sLast = (old == KSPLIT - 1) ? 1 : 0;
        }
        __syncthreads();
        if (sLast) {
            if (tid == 0) {
                const int need = NCONV * (it + 1);
                while (atomicAdd(&g_cnt, 0) < need) { }
            }
            __syncthreads();
            __threadfence();
            if (tid < 256) {
                const int i = m0 + tid;
                const float ri = g_rowinv[i];
                float L[NCH];
                float m = -1e30f;
#pragma unroll
                for (int c = 0; c < NCH; ++c) {
                    float s = g_part[c * NPIX + i] + g_part[(NCH + c) * NPIX + i]
                            + g_part[(2 * NCH + c) * NPIX + i] + g_part[(3 * NCH + c) * NPIX + i];
                    float l = g_U[c * NPIX + i] + (s * ri) * BSCALE + 2.0f * g_qsf[c * NPIX + i];
                    L[c] = l;
                    m = fmaxf(m, l);
                }
                float se = 0.f;
#pragma unroll
                for (int c = 0; c < NCH; ++c) { L[c] = __expf(L[c] - m); se += L[c]; }
                float inv = 1.0f / se;
#pragma unroll
                for (int c = 0; c < NCH; ++c) {
                    float q = L[c] * inv;
                    g_q[c * NPIX + i] = q;
                    qhW[c * NPIX + i] = __float2half_rn(q * ri);
                    if (it == NITER - 1) out[c * NPIX + i] = q;
                }
            }
            if (tid == 0) g_tick[blockIdx.x] = 0;
        }

        // ================= grid barrier =================
        __syncthreads();
        if (tid == 0) {
            __threadfence();
            int arrived = atomicAdd(&g_bar, 1);
            if (arrived == NCTA - 1) {
                atomicExch(&g_bar, 0);
                atomicAdd(&g_gen, 1);
            }
            while (atomicAdd(&g_gen, 0) < it + 1) { }
        }
        __syncthreads();
        __threadfence();
    }
}

// ---------------- launch ----------------
extern "C" void kernel_launch(void* const* d_in, const int* in_sizes, int n_in,
                              void* d_out, int out_size) {
    const float* unary = nullptr;
    const float* ref = nullptr;
    const float* kstd = nullptr;
    for (int i = 0; i < n_in; ++i) {
        if (in_sizes[i] == NCH * NPIX) unary = (const float*)d_in[i];
        else if (in_sizes[i] == 3 * NPIX) ref = (const float*)d_in[i];
        else if (in_sizes[i] == 5) kstd = (const float*)d_in[i];
    }

    cudaFuncSetAttribute(k_fused, cudaFuncAttributeMaxDynamicSharedMemorySize, DYN_SMEM);

    k_K<<<dim3(RP, RP), 256>>>(ref, kstd);
    k_init<<<(NPIX + 255) / 256, 256>>>(unary);
    k_fused<<<dim3(GTILES, KSPLIT), 512, DYN_SMEM>>>((float*)d_out);
}

// round 17
// speedup vs baseline: 1.0629x; 1.0629x over previous
#include <cuda_runtime.h>
#include <cuda_fp16.h>
#include <math.h>
#include <cstdint>

#define HW      96
#define NPIX    9216
#define NCH     21
#define RAD     35
#define KW      71
#define KSPLIT  4
#define KSLICE  2304
#define CHUNK   128
#define NCHUNK  18
#define NSTAGE  3
#define A_STRIDE 144
#define A_PANEL (256 * A_STRIDE)
#define B_PANEL 4096
#define STAGE_BYTES (A_PANEL + 2 * B_PANEL)  // 45056
#define RP      72
#define NTRI    (RP * (RP + 1) / 2)          // 2628
#define GTILES  36
#define NCTA    (GTILES * KSPLIT)            // 144
#define DYN_SMEM (NSTAGE * STAGE_BYTES + 1024)
#define STRIPS  6
#define SROWS   16
#define HALO    86
#define TROW    (HW + 2 * RAD)
#define NCONV   (NCH * STRIPS)
#define NITER   5
#define BSCALE  (4.0f / 255.0f)

// ---------------- device scratch ----------------
__device__ unsigned char g_Ku[(size_t)NPIX * NPIX];
__device__ float  g_rowpart[NPIX * RP];
__device__ float  g_rowinv[NPIX];
__device__ float  g_U[NCH * NPIX];
__device__ float  g_q[NCH * NPIX];
__device__ __half g_qh0[32 * NPIX];
__device__ __half g_qh1[32 * NPIX];
__device__ float  g_part[KSPLIT * NCH * NPIX];
__device__ float  g_qsf[NCH * NPIX];
__device__ float  g_g1d[KW];
__device__ int    g_tick[GTILES];
__device__ int    g_cnt;
__device__ int    g_bar;
__device__ int    g_gen;

// ---------------- PTX helpers ----------------
__device__ __forceinline__ uint32_t s2u(const void* p) {
    uint32_t a;
    asm("{ .reg .u64 t; cvta.to.shared.u64 t, %1; cvt.u32.u64 %0, t; }" : "=r"(a) : "l"(p));
    return a;
}
#define SWZ(b) ((b) ^ (((b) >> 3) & 0x70))
#define CP16(dst, src) \
    asm volatile("cp.async.cg.shared.global [%0], [%1], 16;" :: "r"(dst), "l"(src) : "memory")
#define CP_COMMIT() asm volatile("cp.async.commit_group;" ::: "memory")
#define CP_WAIT(n)  asm volatile("cp.async.wait_group %0;" :: "n"(n) : "memory")
#define BARG() asm volatile("bar.sync 1, 256;" ::: "memory")
#define BARC() asm volatile("bar.sync 2, 256;" ::: "memory")
#define LDSU16(r, addr) \
    asm volatile("ld.shared.u16 %0, [%1];" : "=r"(r) : "r"(addr))
#define LDSM4(r0, r1, r2, r3, addr) \
    asm volatile("ldmatrix.sync.aligned.m8n8.x4.shared.b16 {%0,%1,%2,%3}, [%4];" \
                 : "=r"(r0), "=r"(r1), "=r"(r2), "=r"(r3) : "r"(addr))
#define LDSM2(r0, r1, addr) \
    asm volatile("ldmatrix.sync.aligned.m8n8.x2.shared.b16 {%0,%1}, [%2];" \
                 : "=r"(r0), "=r"(r1) : "r"(addr))
#define MMA16816(d, a0, a1, a2, a3, b0, b1) \
    asm volatile("mma.sync.aligned.m16n8k16.row.col.f32.f16.f16.f32 " \
                 "{%0,%1,%2,%3}, {%4,%5,%6,%7}, {%8,%9}, {%0,%1,%2,%3};" \
                 : "+f"((d)[0]), "+f"((d)[1]), "+f"((d)[2]), "+f"((d)[3]) \
                 : "r"(a0), "r"(a1), "r"(a2), "r"(a3), "r"(b0), "r"(b1))
#define PRMT(d, a, b, sel) \
    asm("prmt.b32 %0, %1, %2, %3;" : "=r"(d) : "r"(a), "r"(b), "n"(sel))

__device__ __forceinline__ uint32_t u8x2_to_h2(uint32_t w) {
    uint32_t r;
    asm("prmt.b32 %0, %1, 0, 0x4140;" : "=r"(r) : "r"(w));
    r |= 0x64006400u;
    asm("sub.rn.f16x2 %0, %0, %1;" : "+r"(r) : "r"(0x64006400u));
    return r;
}

// ---------------- setup: symmetric K, register-packed, PRMT transpose ----------------
__global__ void __launch_bounds__(256) k_K(const float* __restrict__ ref,
                                           const float* __restrict__ kstd) {
    // triangular decode
    int idx = blockIdx.x, a = 0;
    while (idx >= RP - a) { idx -= RP - a; ++a; }
    const int b = a + idx;

    __shared__ float fA[5][128], fB[5][128], nA[128], nB[128];
    __shared__ uint32_t sT32[128][32];       // packed tile, col-rotated (+r>>2)
    __shared__ float redC[16][128];
    const int tid = threadIdx.x;
    const int tr = tid >> 4, tc = tid & 15;

    {
        int half = tid >> 7;
        int l = tid & 127;
        int i = (half ? b : a) * 128 + l;
        int y = i / HW, x = i % HW;
        float f0 = (float)y / kstd[0];
        float f1 = (float)x / kstd[1];
        float f2 = ref[0 * NPIX + i] / kstd[2];
        float f3 = ref[1 * NPIX + i] / kstd[3];
        float f4 = ref[2 * NPIX + i] / kstd[4];
        float nh = -0.5f * (f0 * f0 + f1 * f1 + f2 * f2 + f3 * f3 + f4 * f4);
        if (half == 0) {
            fA[0][l] = f0; fA[1][l] = f1; fA[2][l] = f2; fA[3][l] = f3; fA[4][l] = f4;
            nA[l] = nh;
        } else {
            fB[0][l] = f0; fB[1][l] = f1; fB[2][l] = f2; fB[3][l] = f3; fB[4][l] = f4;
            nB[l] = nh;
        }
    }
    __syncthreads();

    float rf[5][8], nri[8];
#pragma unroll
    for (int i = 0; i < 8; ++i) {
#pragma unroll
        for (int d = 0; d < 5; ++d) rf[d][i] = fA[d][tr * 8 + i];
        nri[i] = nA[tr * 8 + i];
    }
    float rs[8];
    uint32_t pk[8][2];
#pragma unroll
    for (int i = 0; i < 8; ++i) { rs[i] = 0.f; pk[i][0] = 0u; pk[i][1] = 0u; }

#pragma unroll
    for (int jj = 0; jj < 8; ++jj) {
        const int c = tc * 8 + jj;
        const float c0 = fB[0][c], c1 = fB[1][c], c2 = fB[2][c],
                    c3 = fB[3][c], c4 = fB[4][c];
        const float ncj = nB[c];
        float cs = 0.f;
#pragma unroll
        for (int i = 0; i < 8; ++i) {
            float dot = nri[i] + ncj;
            dot = fmaf(rf[0][i], c0, dot);
            dot = fmaf(rf[1][i], c1, dot);
            dot = fmaf(rf[2][i], c2, dot);
            dot = fmaf(rf[3][i], c3, dot);
            dot = fmaf(rf[4][i], c4, dot);
            float v = __expf(dot);
            rs[i] += v;
            cs += v;
            pk[i][jj >> 2] |= __float2uint_rn(v * 255.0f) << (8 * (jj & 3));
        }
        redC[tr][c] = cs;
    }

    // row sums: butterfly over tc (lane bits 0-3); tr is lane bit 4, untouched
#pragma unroll
    for (int i = 0; i < 8; ++i) {
#pragma unroll
        for (int o = 8; o; o >>= 1) rs[i] += __shfl_xor_sync(0xffffffffu, rs[i], o);
    }
    if (tc == 0) {
#pragma unroll
        for (int i = 0; i < 8; ++i)
            g_rowpart[(a * 128 + tr * 8 + i) * RP + b] = rs[i];
    }

    // normal tile: direct register->gmem (uint2, coalesced)
#pragma unroll
    for (int i = 0; i < 8; ++i) {
        const int row = a * 128 + tr * 8 + i;
        *(uint2*)(g_Ku + (size_t)row * NPIX + b * 128 + tc * 8) =
            make_uint2(pk[i][0], pk[i][1]);
    }

    if (a != b) {
        // stage packed words for transpose (col-rotation swizzle)
#pragma unroll
        for (int i = 0; i < 8; ++i) {
            const int r = tr * 8 + i;
#pragma unroll
            for (int d = 0; d < 2; ++d)
                sT32[r][(tc * 2 + d + (r >> 2)) & 31] = pk[i][d];
        }
    }
    __syncthreads();

    // column sums -> rowpart of b
    if (a != b && tid < 128) {
        float sC = 0.f;
#pragma unroll
        for (int k = 0; k < 16; ++k) sC += redC[k][tid];
        g_rowpart[(b * 128 + tid) * RP + a] = sC;
    }

    if (a != b) {
        // PRMT 4x4 byte transpose: 4 cells/thread
        const int lane = tid & 31;
        const int r0 = lane * 4;
#pragma unroll
        for (int cell = 0; cell < 4; ++cell) {
            const int j = (tid >> 5) + 8 * cell;      // u32 col group (cols 4j..4j+3)
            uint32_t w0 = sT32[r0 + 0][(j + lane) & 31];
            uint32_t w1 = sT32[r0 + 1][(j + lane) & 31];
            uint32_t w2 = sT32[r0 + 2][(j + lane) & 31];
            uint32_t w3 = sT32[r0 + 3][(j + lane) & 31];
            uint32_t t01a, t01b, t23a, t23b, o0, o1, o2, o3;
            PRMT(t01a, w0, w1, 0x5140);
            PRMT(t01b, w0, w1, 0x7362);
            PRMT(t23a, w2, w3, 0x5140);
            PRMT(t23b, w2, w3, 0x7362);
            PRMT(o0, t01a, t23a, 0x5410);
            PRMT(o1, t01a, t23a, 0x7632);
            PRMT(o2, t01b, t23b, 0x5410);
            PRMT(o3, t01b, t23b, 0x7632);
            unsigned char* base = g_Ku + (size_t)(b * 128 + 4 * j) * NPIX + a * 128 + r0;
            *(uint32_t*)(base) = o0;
            *(uint32_t*)(base + NPIX) = o1;
            *(uint32_t*)(base + 2 * NPIX) = o2;
            *(uint32_t*)(base + 3 * NPIX) = o3;
        }
    }
}

__global__ void k_init(const float* __restrict__ unary) {
    int i = blockIdx.x * blockDim.x + threadIdx.x;
    if (i >= NPIX) return;
    if (i == 0) { g_cnt = 0; g_bar = 0; g_gen = 0; }
    if (i < GTILES) g_tick[i] = 0;
    if (i == 0) {
        float w[KW]; float s = 0.f;
        for (int t = 0; t < KW; ++t) {
            float d = (float)t - (float)RAD;
            w[t] = expf(-(d * d) / 72.0f); s += w[t];
        }
        float inv = 1.0f / s;
        for (int t = 0; t < KW; ++t) g_g1d[t] = w[t] * inv;
    }
    float s = 0.f;
    const float* p = g_rowpart + i * RP;
#pragma unroll
    for (int bq = 0; bq < RP; ++bq) s += p[bq];
    float ri = 1.0f / (sqrtf(s) + 1e-8f);
    g_rowinv[i] = ri;

    float L[NCH];
    float m = -1e30f;
#pragma unroll
    for (int c = 0; c < NCH; ++c) {
        float u = unary[c * NPIX + i];
        u = fminf(fmaxf(u, 1e-5f), 1.0f);
        float lu = logf(u);
        g_U[c * NPIX + i] = lu;
        L[c] = lu;
        m = fmaxf(m, lu);
    }
    float se = 0.f;
#pragma unroll
    for (int c = 0; c < NCH; ++c) { L[c] = __expf(L[c] - m); se += L[c]; }
    float inv = 1.0f / se;
#pragma unroll
    for (int c = 0; c < NCH; ++c) {
        float q = L[c] * inv;
        g_q[c * NPIX + i] = q;
        g_qh0[c * NPIX + i] = __float2half_rn(q * ri);
    }
#pragma unroll
    for (int c = NCH; c < 32; ++c) {
        g_qh0[c * NPIX + i] = __float2half_rn(0.f);
        g_qh1[c * NPIX + i] = __float2half_rn(0.f);
    }
}

// ---------------- persistent fused: 5 iterations, in-kernel grid barrier ----------------
__global__ void __launch_bounds__(512, 1) k_fused(float* __restrict__ out) {
    extern __shared__ char dynRaw[];
    __shared__ float sImg[HALO * HW];
    __shared__ float sTmp[SROWS * TROW];
    __shared__ float sWc[KW];
    __shared__ int sLast;

    const uint32_t dynb = (s2u(dynRaw) + 1023u) & ~1023u;
    const int tid = threadIdx.x;
    const int m0 = blockIdx.x * 256;
    const int bid = blockIdx.y * GTILES + blockIdx.x;

    for (int it = 0; it < NITER; ++it) {
        const int p = it & 1;
        const __half* qhR = p ? g_qh1 : g_qh0;
        __half* qhW = p ? g_qh0 : g_qh1;

        if (tid < 256) {
            const int w = tid >> 5, lid = tid & 31;
            const int zbase = blockIdx.y * KSLICE;
            const unsigned char* Abase = g_Ku + (size_t)m0 * NPIX + zbase;
            const __half* Bbase = qhR + zbase;

            auto load_chunk = [&](int ci) {
                const uint32_t stage = dynb + (uint32_t)(ci % NSTAGE) * STAGE_BYTES;
                const int koff = ci * CHUNK;
#pragma unroll
                for (int u = tid; u < 2560; u += 256) {
                    uint32_t dst; const void* src;
                    if (u < 2048) {
                        int r = u >> 3, t = u & 7;
                        src = Abase + (size_t)r * NPIX + koff + t * 16;
                        dst = stage + (uint32_t)(r * A_STRIDE + t * 16);
                    } else {
                        int v = u - 2048;
                        int pl = v >> 8, cc = (v >> 3) & 31, t = v & 7;
                        src = Bbase + (size_t)cc * NPIX + koff + pl * 64 + t * 8;
                        dst = stage + A_PANEL + (uint32_t)pl * B_PANEL
                            + SWZ((uint32_t)(cc * 128 + t * 16));
                    }
                    CP16(dst, src);
                }
                CP_COMMIT();
            };

            float acc[2][3][4];
#pragma unroll
            for (int f = 0; f < 2; ++f)
#pragma unroll
                for (int g = 0; g < 3; ++g)
#pragma unroll
                    for (int k = 0; k < 4; ++k) acc[f][g][k] = 0.f;

            for (int i = 0; i < NSTAGE - 1; ++i) load_chunk(i);

            const uint32_t aBase0 = (uint32_t)((w * 32 + (lid >> 2)) * A_STRIDE + (lid & 3) * 2);
            const uint32_t aBase1 = aBase0 + 16 * A_STRIDE;
            const uint32_t bRowOff01 = (uint32_t)(((lid & 7) + ((lid >> 4) << 3)) * 128) + (((lid >> 3) & 1) << 4);
            const uint32_t bRowOff2 = (uint32_t)((16 + (lid & 7)) * 128) + (((lid >> 3) & 1) << 4);

            for (int i = 0; i < NCHUNK; ++i) {
                if (i + NSTAGE - 1 < NCHUNK) CP_WAIT(NSTAGE - 2); else CP_WAIT(0);
                BARG();
                if (i + NSTAGE - 1 < NCHUNK) load_chunk(i + NSTAGE - 1);

                const uint32_t stage = dynb + (uint32_t)(i % NSTAGE) * STAGE_BYTES;
#pragma unroll
                for (int pl = 0; pl < 2; ++pl) {
                    const uint32_t aOff = stage + (uint32_t)pl * 64;
                    const uint32_t bufB = stage + A_PANEL + (uint32_t)pl * B_PANEL;
#pragma unroll
                    for (int ks = 0; ks < 4; ++ks) {
                        const uint32_t kb = (uint32_t)ks * 32;
                        uint32_t b00, b01, b10, b11, b20, b21;
                        LDSM4(b00, b01, b10, b11, bufB + SWZ(bRowOff01 + kb));
                        LDSM2(b20, b21, bufB + SWZ(bRowOff2 + kb));

                        const uint32_t ad0 = aOff + aBase0 + (uint32_t)ks * 16;
                        const uint32_t ad1 = aOff + aBase1 + (uint32_t)ks * 16;
                        uint32_t w0, w1, w2, w3, w4, w5, w6, w7;
                        LDSU16(w0, ad0);
                        LDSU16(w1, ad0 + 8 * A_STRIDE);
                        LDSU16(w2, ad0 + 8);
                        LDSU16(w3, ad0 + 8 * A_STRIDE + 8);
                        LDSU16(w4, ad1);
                        LDSU16(w5, ad1 + 8 * A_STRIDE);
                        LDSU16(w6, ad1 + 8);
                        LDSU16(w7, ad1 + 8 * A_STRIDE + 8);
                        const uint32_t a00 = u8x2_to_h2(w0);
                        const uint32_t a01 = u8x2_to_h2(w1);
                        const uint32_t a02 = u8x2_to_h2(w2);
                        const uint32_t a03 = u8x2_to_h2(w3);
                        const uint32_t a10 = u8x2_to_h2(w4);
                        const uint32_t a11 = u8x2_to_h2(w5);
                        const uint32_t a12 = u8x2_to_h2(w6);
                        const uint32_t a13 = u8x2_to_h2(w7);

                        MMA16816(acc[0][0], a00, a01, a02, a03, b00, b01);
                        MMA16816(acc[0][1], a00, a01, a02, a03, b10, b11);
                        MMA16816(acc[0][2], a00, a01, a02, a03, b20, b21);
                        MMA16816(acc[1][0], a10, a11, a12, a13, b00, b01);
                        MMA16816(acc[1][1], a10, a11, a12, a13, b10, b11);
                        MMA16816(acc[1][2], a10, a11, a12, a13, b20, b21);
                    }
                }
            }

            const int c0 = (lid & 3) * 2;
            float* pp = g_part + (size_t)blockIdx.y * (NCH * NPIX);
#pragma unroll
            for (int f = 0; f < 2; ++f) {
                const int row0 = m0 + w * 32 + f * 16 + (lid >> 2);
#pragma unroll
                for (int g = 0; g < 3; ++g) {
#pragma unroll
                    for (int k = 0; k < 4; ++k) {
                        int c = g * 8 + c0 + (k & 1);
                        int row = row0 + ((k >> 1) << 3);
                        if (c < NCH) pp[c * NPIX + row] = acc[f][g][k];
                    }
                }
            }
            __threadfence();
        } else if (bid < NCONV) {
            const int ctid = tid - 256;
            const int c = bid / STRIPS, strip = bid % STRIPS;
            const int y0 = strip * SROWS, rowLo = y0 - RAD;

            if (ctid < KW) sWc[ctid] = g_g1d[ctid];
            const float* src = g_q + c * NPIX;
            for (int px = ctid; px < HALO * HW; px += 256) {
                int r = px / HW, x = px - r * HW;
                int gr = rowLo + r;
                sImg[px] = (gr >= 0 && gr < HW) ? src[gr * HW + x] : 0.f;
            }
            for (int px = ctid; px < SROWS * TROW; px += 256) sTmp[px] = 0.f;
            BARC();

            float a[6];
#pragma unroll
            for (int j = 0; j < 6; ++j) a[j] = 0.f;
#pragma unroll
            for (int t = 0; t < KW; ++t) {
                const float wv = sWc[t];
                const int o = t * HW + ctid;
#pragma unroll
                for (int j = 0; j < 6; ++j)
                    a[j] = fmaf(wv, sImg[o + 256 * j], a[j]);
            }
#pragma unroll
            for (int j = 0; j < 6; ++j) {
                int px = ctid + 256 * j;
                int y = px / HW, x = px - y * HW;
                sTmp[y * TROW + RAD + x] = a[j];
            }
            BARC();

            int bix[6];
#pragma unroll
            for (int j = 0; j < 6; ++j) {
                int px = ctid + 256 * j;
                int y = px / HW, x = px - y * HW;
                bix[j] = y * TROW + x;
                a[j] = 0.f;
            }
#pragma unroll
            for (int t = 0; t < KW; ++t) {
                const float wv = sWc[t];
#pragma unroll
                for (int j = 0; j < 6; ++j)
                    a[j] = fmaf(wv, sTmp[bix[j] + t], a[j]);
            }
            float* dst = g_qsf + c * NPIX + y0 * HW;
#pragma unroll
            for (int j = 0; j < 6; ++j) dst[ctid + 256 * j] = a[j];
            __threadfence();
            BARC();
            if (ctid == 0) atomicAdd(&g_cnt, 1);
        }

        __syncthreads();
        if (tid == 0) {
            int old = atomicAdd(&g_tick[blockIdx.x], 1);
            sLast = (old == KSPLIT - 1) ? 1 : 0;
        }
        __syncthreads();
        if (sLast) {
            if (tid == 0) {
                const int need = NCONV * (it + 1);
                while (atomicAdd(&g_cnt, 0) < need) { }
            }
            __syncthreads();
            __threadfence();
            if (tid < 256) {
                const int i = m0 + tid;
                const float ri = g_rowinv[i];
                float L[NCH];
                float m = -1e30f;
#pragma unroll
                for (int c = 0; c < NCH; ++c) {
                    float s = g_part[c * NPIX + i] + g_part[(NCH + c) * NPIX + i]
                            + g_part[(2 * NCH + c) * NPIX + i] + g_part[(3 * NCH + c) * NPIX + i];
                    float l = g_U[c * NPIX + i] + (s * ri) * BSCALE + 2.0f * g_qsf[c * NPIX + i];
                    L[c] = l;
                    m = fmaxf(m, l);
                }
                float se = 0.f;
#pragma unroll
                for (int c = 0; c < NCH; ++c) { L[c] = __expf(L[c] - m); se += L[c]; }
                float inv = 1.0f / se;
#pragma unroll
                for (int c = 0; c < NCH; ++c) {
                    float q = L[c] * inv;
                    g_q[c * NPIX + i] = q;
                    qhW[c * NPIX + i] = __float2half_rn(q * ri);
                    if (it == NITER - 1) out[c * NPIX + i] = q;
                }
            }
            if (tid == 0) g_tick[blockIdx.x] = 0;
        }

        __syncthreads();
        if (tid == 0) {
            __threadfence();
            int arrived = atomicAdd(&g_bar, 1);
            if (arrived == NCTA - 1) {
                atomicExch(&g_bar, 0);
                atomicAdd(&g_gen, 1);
            }
            while (atomicAdd(&g_gen, 0) < it + 1) { }
        }
        __syncthreads();
        __threadfence();
    }
}

// ---------------- launch ----------------
extern "C" void kernel_launch(void* const* d_in, const int* in_sizes, int n_in,
                              void* d_out, int out_size) {
    const float* unary = nullptr;
    const float* ref = nullptr;
    const float* kstd = nullptr;
    for (int i = 0; i < n_in; ++i) {
        if (in_sizes[i] == NCH * NPIX) unary = (const float*)d_in[i];
        else if (in_sizes[i] == 3 * NPIX) ref = (const float*)d_in[i];
        else if (in_sizes[i] == 5) kstd = (const float*)d_in[i];
    }

    cudaFuncSetAttribute(k_fused, cudaFuncAttributeMaxDynamicSharedMemorySize, DYN_SMEM);

    k_K<<<NTRI, 256>>>(ref, kstd);
    k_init<<<(NPIX + 255) / 256, 256>>>(unary);
    k_fused<<<dim3(GTILES, KSPLIT), 512, DYN_SMEM>>>((float*)d_out);
}